// round 17
// baseline (speedup 1.0000x reference)
#include <cuda_runtime.h>
#include <cuda_bf16.h>

#define Bn 2
#define Cc 32
#define Hh 32
#define Nn 128
#define Ff 32
#define Ee 16256          // N*(N-1)
#define NM1 127
#define LN_EPS 1e-5f

// ---------------- scratch (device globals; no allocation) ----------------
__device__ float g_A  [Bn*Hh*Nn*Ff];   // fc1(conv(sender-part))
__device__ float g_Bc [Bn*Hh*Nn*Ff];   // fc1(conv(receiver-part)) + bias terms
__device__ float g_X  [Bn*Hh*Ee*Ff];   // pre-LN edge activations (133 MB)
__device__ float g_part[Bn*Hh*Nn*2];   // per-(b,h,r) partial (sum, sumsq)
__device__ float g_att [Bn*Ee*Ff];     // attention (4.2 MB)
__device__ float g_inc [Bn*Hh*Nn*Ff];  // incoming (already /N)
__device__ float g_incm[Bn*Hh*Nn*Ff];  // incoming after node MLP

__device__ __forceinline__ float silu_f(float x) {
    return x * __frcp_rn(1.f + __expf(-x));
}
__device__ __forceinline__ float sigm_f(float x) {
    return __frcp_rn(1.f + __expf(-x));
}

// ---------------- K1: per-node A / Bc precompute ----------------
__global__ void k1_node_pre(const float* __restrict__ node,
                            const float* __restrict__ ecw,
                            const float* __restrict__ ecb,
                            const float* __restrict__ f1w,
                            const float* __restrict__ f1b) {
    int bid = blockIdx.x;                 // (b,h,n) linear
    int n = bid & (Nn-1);
    int h = (bid >> 7) & (Hh-1);
    int b = bid >> 12;
    int g = threadIdx.x;

    const float* np_ = node + ((b*Cc)*Nn + n)*Ff + g;
    const float* w   = ecw + h*2*Cc;
    float S = 0.f, R = 0.f;
#pragma unroll
    for (int c = 0; c < Cc; c++) {
        float v = np_[c*Nn*Ff];
        S += w[c]      * v;
        R += w[Cc + c] * v;
    }
    float A0=0.f,A1=0.f,A2=0.f,A3=0.f, B0=0.f,B1=0.f,B2=0.f,B3=0.f, rs=0.f;
#pragma unroll
    for (int f = 0; f < Ff; f += 4) {
        float w0 = f1w[g*Ff + f+0], w1 = f1w[g*Ff + f+1];
        float w2_ = f1w[g*Ff + f+2], w3 = f1w[g*Ff + f+3];
        A0 += w0 * __shfl_sync(0xffffffffu, S, f+0);
        A1 += w1 * __shfl_sync(0xffffffffu, S, f+1);
        A2 += w2_ * __shfl_sync(0xffffffffu, S, f+2);
        A3 += w3 * __shfl_sync(0xffffffffu, S, f+3);
        B0 += w0 * __shfl_sync(0xffffffffu, R, f+0);
        B1 += w1 * __shfl_sync(0xffffffffu, R, f+1);
        B2 += w2_ * __shfl_sync(0xffffffffu, R, f+2);
        B3 += w3 * __shfl_sync(0xffffffffu, R, f+3);
        rs += w0 + w1 + w2_ + w3;
    }
    int o = ((b*Hh + h)*Nn + n)*Ff + g;
    g_A [o] = (A0+A1)+(A2+A3);
    g_Bc[o] = (B0+B1)+(B2+B3) + ecb[h]*rs + f1b[g];
}

// ---------------- K2: edge pass A — phase-split + register-tiled fc2 GEMM ----------------
// block = (b,h,r), 256 threads.
// Phase A: lane = q; thread computes 4 consecutive e -> one conflict-free STS.128.
// Phase B: warp = 16 edges; lane = (le,lf); 4e x 4f tile; 2 LDS.128 + 16 FMA per q.
__global__ void k2_edgeA(const float* __restrict__ f2w,
                         const float* __restrict__ f2b) {
    int bid = blockIdx.x;                 // (b,h,r)
    int r = bid & (Nn-1);
    int h = (bid >> 7) & (Hh-1);
    int b = bid >> 12;
    int tid = threadIdx.x;
    int bh = b*Hh + h;
    int lane = tid & 31, w = tid >> 5;

    __shared__ __align__(16) float uT[32*132];   // q rows (stride 132), e cols; 16.9 KB
    __shared__ __align__(16) float w2T[32*32];   // w2T[q][f] = f2w[f][q]; 4 KB
    __shared__ float sm[16];

    for (int i = tid; i < Ff*Ff; i += 256) {     // transpose f2w into smem
        int f = i >> 5, q = i & 31;
        w2T[q*Ff + f] = f2w[i];
    }

    // ---- phase A: u = silu(A[s]+Bc[r]); lane = q, 4 e per thread, STS.128 ----
    {
        float bcq = g_Bc[(bh*Nn + r)*Ff + lane];
        const float* Ab = g_A + (size_t)bh*Nn*Ff + lane;
        for (int cc = w; cc < 32; cc += 8) {
            int e0 = cc*4;
            float4 u;
            int s0 = e0+0 + (e0+0 >= r);
            int s1_ = e0+1 + (e0+1 >= r);
            int s2_ = e0+2 + (e0+2 >= r);
            float v0 = Ab[s0*Ff], v1 = Ab[s1_*Ff], v2 = Ab[s2_*Ff];
            u.x = silu_f(v0 + bcq);
            u.y = silu_f(v1 + bcq);
            u.z = silu_f(v2 + bcq);
            if (e0+3 < NM1) {
                int s3 = e0+3 + (e0+3 >= r);
                u.w = silu_f(Ab[s3*Ff] + bcq);
            } else u.w = 0.f;
            *(float4*)&uT[lane*132 + e0] = u;
        }
    }
    __syncthreads();

    // ---- phase B: register-tiled GEMM ----
    int le = lane >> 3, lf = lane & 7;
    int e0 = w*16 + le*4;                 // 4 edges e0..e0+3 (e0 max 124)
    int f0 = lf*4;

    float acc[4][4];
#pragma unroll
    for (int i = 0; i < 4; i++)
#pragma unroll
        for (int j = 0; j < 4; j++) acc[i][j] = 0.f;

    const float* uTb = uT + e0;
    const float* wTb = w2T + f0;
#pragma unroll 8
    for (int q = 0; q < 32; q++) {
        float4 uu = *(const float4*)(uTb + q*132);
        float4 wv = *(const float4*)(wTb + q*Ff);
        acc[0][0] += uu.x*wv.x; acc[0][1] += uu.x*wv.y; acc[0][2] += uu.x*wv.z; acc[0][3] += uu.x*wv.w;
        acc[1][0] += uu.y*wv.x; acc[1][1] += uu.y*wv.y; acc[1][2] += uu.y*wv.z; acc[1][3] += uu.y*wv.w;
        acc[2][0] += uu.z*wv.x; acc[2][1] += uu.z*wv.y; acc[2][2] += uu.z*wv.z; acc[2][3] += uu.z*wv.w;
        acc[3][0] += uu.w*wv.x; acc[3][1] += uu.w*wv.y; acc[3][2] += uu.w*wv.z; acc[3][3] += uu.w*wv.w;
    }

    float b20 = f2b[f0+0], b21 = f2b[f0+1], b22 = f2b[f0+2], b23 = f2b[f0+3];
    float s1 = 0.f, s2 = 0.f;
    size_t ebase = (size_t)bh*Ee + (size_t)r*NM1;
#pragma unroll
    for (int i = 0; i < 4; i++) {
        int e = e0 + i;
        if (e < NM1) {
            float4 x;
            x.x = silu_f(acc[i][0] + b20);
            x.y = silu_f(acc[i][1] + b21);
            x.z = silu_f(acc[i][2] + b22);
            x.w = silu_f(acc[i][3] + b23);
            *(float4*)&g_X[(ebase + e)*Ff + f0] = x;
            s1 += (x.x + x.y) + (x.z + x.w);
            s2 += (x.x*x.x + x.y*x.y) + (x.z*x.z + x.w*x.w);
        }
    }

    // ---- stats reduce ----
#pragma unroll
    for (int o = 16; o; o >>= 1) {
        s1 += __shfl_down_sync(0xffffffffu, s1, o);
        s2 += __shfl_down_sync(0xffffffffu, s2, o);
    }
    if (lane == 0) { sm[w] = s1; sm[8 + w] = s2; }
    __syncthreads();
    if (tid == 0) {
        float t1 = 0.f, t2 = 0.f;
#pragma unroll
        for (int q = 0; q < 8; q++) { t1 += sm[q]; t2 += sm[8+q]; }
        g_part[(bh*Nn + r)*2 + 0] = t1;
        g_part[(bh*Nn + r)*2 + 1] = t2;
    }
}

// ---------------- K4a: attention (h-reduction factored out; stats derived locally) ----------------
__global__ void k4a_att(const float* __restrict__ emask,
                        const float* __restrict__ lng,
                        const float* __restrict__ lnb,
                        const float* __restrict__ attw,
                        const float* __restrict__ attb) {
    int b  = blockIdx.y;
    int i4 = blockIdx.x * blockDim.x + threadIdx.x;   // float4 index into (E,F)
    int tid = threadIdx.x;

    __shared__ float smu[Hh], sinv[Hh], swh[Hh];
    __shared__ float sc[2];                            // c1, c0

    // local LN-stats finalize from g_part: thread (h = tid>>3, k = tid&7)
    {
        int h = tid >> 3, k = tid & 7;
        const float* pp = g_part + ((size_t)(b*Hh + h)*Nn + k*16)*2;
        float p1 = 0.f, p2 = 0.f;
#pragma unroll
        for (int i = 0; i < 16; i++) { p1 += pp[2*i]; p2 += pp[2*i+1]; }
#pragma unroll
        for (int o = 4; o; o >>= 1) {
            p1 += __shfl_down_sync(0xffffffffu, p1, o);
            p2 += __shfl_down_sync(0xffffffffu, p2, o);
        }
        if (k == 0) {
            const float invc = 1.f / (float)(Ee * Ff);
            float mu  = p1 * invc;
            float var = p2 * invc - mu*mu;
            smu[h]  = mu;
            sinv[h] = rsqrtf(var + LN_EPS);
        }
    }
    __syncthreads();
    if (tid < Hh) swh[tid] = attw[tid] * sinv[tid];
    __syncthreads();
    if (tid == 0) {
        float c1 = 0.f, c0 = 0.f;
#pragma unroll
        for (int h = 0; h < Hh; h++) { c1 += swh[h]*smu[h]; c0 += attw[h]; }
        sc[0] = c1; sc[1] = c0;
    }
    __syncthreads();

    const float4* xb = (const float4*)(g_X + (size_t)b*Hh*Ee*Ff) + i4;
    float4 T = make_float4(0.f, 0.f, 0.f, 0.f);
#pragma unroll
    for (int h = 0; h < Hh; h++) {
        float wv = swh[h];
        float4 x = xb[(size_t)h * (Ee*Ff/4)];
        T.x += wv*x.x; T.y += wv*x.y; T.z += wv*x.z; T.w += wv*x.w;
    }
    float c1 = sc[0], c0 = sc[1];
    float ab = attb[0];
    int e = i4 >> 3;                                  // 8 float4 per edge row
    float em = emask[b*Ee + e];
    float4 lg = ((const float4*)lng)[i4];
    float4 lb = ((const float4*)lnb)[i4];
    float4 a;
    a.x = sigm_f(em*(lg.x*(T.x - c1) + lb.x*c0) + ab);
    a.y = sigm_f(em*(lg.y*(T.y - c1) + lb.y*c0) + ab);
    a.z = sigm_f(em*(lg.z*(T.z - c1) + lb.z*c0) + ab);
    a.w = sigm_f(em*(lg.w*(T.w - c1) + lb.w*c0) + ab);
    ((float4*)(g_att + (size_t)b*Ee*Ff))[i4] = a;
}

// ---------------- K4b: mij out + segmented incoming — 256 thr, stats local ----------------
__global__ void k4b_edgeB(const float* __restrict__ emask,
                          const float* __restrict__ lng,
                          const float* __restrict__ lnb,
                          float* __restrict__ out_mij) {
    int bid = blockIdx.x;
    int r = bid & (Nn-1);
    int h = (bid >> 7) & (Hh-1);
    int b = bid >> 12;
    int tid = threadIdx.x;
    int f4  = tid & 7;                    // which float4 of the 32-f row
    int bh = b*Hh + h;

    // 16B-aligned smem FIRST (float4-accessed), scalars after.
    __shared__ __align__(16) float sacc[256*4];
    __shared__ float sstat[2];

    if (tid < 32) {
        float p1 = 0.f, p2 = 0.f;
        for (int rr = tid; rr < Nn; rr += 32) {
            p1 += g_part[(bh*Nn + rr)*2 + 0];
            p2 += g_part[(bh*Nn + rr)*2 + 1];
        }
#pragma unroll
        for (int o = 16; o; o >>= 1) {
            p1 += __shfl_down_sync(0xffffffffu, p1, o);
            p2 += __shfl_down_sync(0xffffffffu, p2, o);
        }
        if (tid == 0) {
            const float invc = 1.f / (float)(Ee * Ff);
            float mu  = p1 * invc;
            float var = p2 * invc - mu*mu;
            sstat[0] = mu;
            sstat[1] = rsqrtf(var + LN_EPS);
        }
    }
    __syncthreads();
    float mu  = sstat[0];
    float inv = sstat[1];

    const float4* xb  = (const float4*)(g_X    + (size_t)bh*Ee*Ff);
    float4*       mo  = (float4*)      (out_mij + (size_t)bh*Ee*Ff);
    const float4* atp = (const float4*)(g_att  + (size_t)b*Ee*Ff);
    const float4* lgp = (const float4*)lng;
    const float4* lbp = (const float4*)lnb;
    const float*  emb = emask + b*Ee;

    int e0 = r*NM1;
    int jr = tid >> 3;                    // 0..31
    float4 acc = make_float4(0.f, 0.f, 0.f, 0.f);
#pragma unroll
    for (int j = jr; j < NM1; j += 32) {
        int e = e0 + j;
        int o = e*8 + f4;
        float  em = emb[e];
        float4 x  = xb[o];
        float4 lg = lgp[o];
        float4 lb = lbp[o];
        float4 at = atp[o];
        float4 m1, mv;
        m1.x = ((x.x - mu)*inv*lg.x + lb.x) * em;
        m1.y = ((x.y - mu)*inv*lg.y + lb.y) * em;
        m1.z = ((x.z - mu)*inv*lg.z + lb.z) * em;
        m1.w = ((x.w - mu)*inv*lg.w + lb.w) * em;
        mv.x = m1.x * em; mv.y = m1.y * em; mv.z = m1.z * em; mv.w = m1.w * em;
        mo[o] = mv;
        acc.x += m1.x * at.x * em;
        acc.y += m1.y * at.y * em;
        acc.z += m1.z * at.z * em;
        acc.w += m1.w * at.w * em;
    }

    *(float4*)&sacc[tid*4] = acc;
    __syncthreads();
    if (tid < 32) {
        int c = tid >> 2, comp = tid & 3; // f = c*4 + comp == tid
        float t = 0.f;
#pragma unroll
        for (int k = 0; k < 32; k++) t += sacc[(k*8 + c)*4 + comp];
        g_inc[(bh*Nn + r)*Ff + tid] = t * (1.f/(float)Nn);
    }
}

// ---------------- node-side MLP4d: one block per (b,h'), whole LN in-block ----------------
template<int MODE>
__global__ void k_node_mlp(const float* __restrict__ node,
                           const float* __restrict__ cw,
                           const float* __restrict__ cb,
                           const float* __restrict__ f1w,
                           const float* __restrict__ f1b,
                           const float* __restrict__ f2w,
                           const float* __restrict__ f2b,
                           const float* __restrict__ lg,
                           const float* __restrict__ lb,
                           const float* __restrict__ nmask,
                           float* __restrict__ out) {
    int hp = blockIdx.x & (Hh-1);
    int b  = blockIdx.x >> 5;
    int f  = threadIdx.x & 31;
    int w  = threadIdx.x >> 5;            // 0..3

    const int NCH = (MODE == 0) ? Hh : 2*Hh;
    __shared__ float scw[2*Hh];
    __shared__ float su[Nn*Ff];           // 16 KB
    __shared__ float sred[8];
    __shared__ float sstat[2];
    for (int i = threadIdx.x; i < NCH; i += blockDim.x) scw[i] = cw[hp*NCH + i];
    __syncthreads();

    float w1r[Ff], w2r[Ff];
#pragma unroll
    for (int q = 0; q < Ff; q++) { w1r[q] = f1w[f*Ff + q]; w2r[q] = f2w[f*Ff + q]; }
    float cbv = cb[hp], b1 = f1b[f], b2 = f2b[f];

    float s1 = 0.f, s2 = 0.f;
    for (int n = w; n < Nn; n += 4) {
        float y = cbv;
        if (MODE == 0) {
            const float* ip = g_inc + ((b*Hh)*Nn + n)*Ff + f;
#pragma unroll
            for (int h = 0; h < Hh; h++) y += scw[h] * ip[h*Nn*Ff];
        } else {
            const float* ipa = node   + ((b*Cc)*Nn + n)*Ff + f;
            const float* ipb = g_incm + ((b*Hh)*Nn + n)*Ff + f;
#pragma unroll
            for (int c = 0; c < Cc; c++) y += scw[c] * ipa[c*Nn*Ff];
#pragma unroll
            for (int h = 0; h < Hh; h++) y += scw[Cc + h] * ipb[h*Nn*Ff];
        }
        float a0=0.f,a1=0.f,a2=0.f,a3=0.f;
#pragma unroll
        for (int q = 0; q < Ff; q += 4) {
            a0 += __shfl_sync(0xffffffffu, y, q+0) * w1r[q+0];
            a1 += __shfl_sync(0xffffffffu, y, q+1) * w1r[q+1];
            a2 += __shfl_sync(0xffffffffu, y, q+2) * w1r[q+2];
            a3 += __shfl_sync(0xffffffffu, y, q+3) * w1r[q+3];
        }
        float u1 = silu_f(b1 + ((a0+a1)+(a2+a3)));
        a0=a1=a2=a3=0.f;
#pragma unroll
        for (int q = 0; q < Ff; q += 4) {
            a0 += __shfl_sync(0xffffffffu, u1, q+0) * w2r[q+0];
            a1 += __shfl_sync(0xffffffffu, u1, q+1) * w2r[q+1];
            a2 += __shfl_sync(0xffffffffu, u1, q+2) * w2r[q+2];
            a3 += __shfl_sync(0xffffffffu, u1, q+3) * w2r[q+3];
        }
        float u2 = silu_f(b2 + ((a0+a1)+(a2+a3)));
        su[n*Ff + f] = u2;
        s1 += u2; s2 += u2*u2;
    }
#pragma unroll
    for (int o = 16; o; o >>= 1) {
        s1 += __shfl_down_sync(0xffffffffu, s1, o);
        s2 += __shfl_down_sync(0xffffffffu, s2, o);
    }
    if (f == 0) { sred[w] = s1; sred[4 + w] = s2; }
    __syncthreads();
    if (threadIdx.x == 0) {
        float T1 = sred[0] + sred[1] + sred[2] + sred[3];
        float T2 = sred[4] + sred[5] + sred[6] + sred[7];
        const float invc = 1.f / (float)(Nn * Ff);
        float mu  = T1 * invc;
        float var = T2 * invc - mu*mu;
        sstat[0] = mu;
        sstat[1] = rsqrtf(var + LN_EPS);
    }
    __syncthreads();
    float mu = sstat[0], inv = sstat[1];
    for (int n = w; n < Nn; n += 4) {
        float v = (su[n*Ff + f] - mu) * inv * lg[n*Ff + f] + lb[n*Ff + f];
        int oidx = ((b*Hh + hp)*Nn + n)*Ff + f;
        if (MODE == 0) {
            g_incm[oidx] = v;
        } else {
            out[oidx] = v * nmask[b*Nn + n];
        }
    }
}

// ---------------- launch ----------------
extern "C" void kernel_launch(void* const* d_in, const int* in_sizes, int n_in,
                              void* d_out, int out_size) {
    const float* node   = (const float*)d_in[0];
    const float* nmask  = (const float*)d_in[3];
    const float* emask  = (const float*)d_in[4];
    const float* e_cw   = (const float*)d_in[5];
    const float* e_cb   = (const float*)d_in[6];
    const float* e_f1w  = (const float*)d_in[7];
    const float* e_f1b  = (const float*)d_in[8];
    const float* e_f2w  = (const float*)d_in[9];
    const float* e_f2b  = (const float*)d_in[10];
    const float* e_lng  = (const float*)d_in[11];
    const float* e_lnb  = (const float*)d_in[12];
    const float* att_w  = (const float*)d_in[13];
    const float* att_b  = (const float*)d_in[14];
    const float* n_cw   = (const float*)d_in[15];
    const float* n_cb   = (const float*)d_in[16];
    const float* n_f1w  = (const float*)d_in[17];
    const float* n_f1b  = (const float*)d_in[18];
    const float* n_f2w  = (const float*)d_in[19];
    const float* n_f2b  = (const float*)d_in[20];
    const float* n_lng  = (const float*)d_in[21];
    const float* n_lnb  = (const float*)d_in[22];
    const float* ne_cw  = (const float*)d_in[23];
    const float* ne_cb  = (const float*)d_in[24];
    const float* ne_f1w = (const float*)d_in[25];
    const float* ne_f1b = (const float*)d_in[26];
    const float* ne_f2w = (const float*)d_in[27];
    const float* ne_f2b = (const float*)d_in[28];
    const float* ne_lng = (const float*)d_in[29];
    const float* ne_lnb = (const float*)d_in[30];

    float* out_node = (float*)d_out;                       // (B,H,N,F)
    float* out_mij  = (float*)d_out + Bn*Hh*Nn*Ff;         // (B,H,E,F)

    k1_node_pre<<<Bn*Hh*Nn, 32>>>(node, e_cw, e_cb, e_f1w, e_f1b);
    k2_edgeA   <<<Bn*Hh*Nn, 256>>>(e_f2w, e_f2b);
    {
        dim3 grid(Ee*Ff/4/256, Bn);                        // 508 x 2
        k4a_att<<<grid, 256>>>(emask, e_lng, e_lnb, att_w, att_b);
    }
    k4b_edgeB  <<<Bn*Hh*Nn, 256>>>(emask, e_lng, e_lnb, out_mij);  // idx 3 -> profiled
    k_node_mlp<0><<<Bn*Hh, 128>>>(nullptr, n_cw, n_cb, n_f1w, n_f1b,
                                  n_f2w, n_f2b, n_lng, n_lnb, nullptr, nullptr);
    k_node_mlp<1><<<Bn*Hh, 128>>>(node, ne_cw, ne_cb, ne_f1w, ne_f1b,
                                  ne_f2w, ne_f2b, ne_lng, ne_lnb, nmask, out_node);
}